// round 1
// baseline (speedup 1.0000x reference)
#include <cuda_runtime.h>

// ---------------------------------------------------------------------------
// PhongCircleRenderer
//
// Inputs (metadata order):
//   0: idx         int32   [B,H,W,K]   B=8,H=512,W=512,K=8
//   1: points      float32 [P,3]       P = 1,200,000
//   2: features    float32 [P,3]
//   3: normals     float32 [P,3]
//   4: cam_centers float32 [B,3]
//   5: cloud_idx   int32   [P]
//   6: light_dir   float32 [3]
// Output: float32 [B,H,W,3]
//
// Math reduction: alpha weights are binary; first valid fragment gets full
// weight and zeroes all later transmittance, and background overrides where
// idx[...,0] < 0. Therefore:
//   out = (idx0 < 0) ? (1,1,1) : shaded[idx0]
// ---------------------------------------------------------------------------

#define P_MAX 1200000

__device__ float4 g_shaded[P_MAX];   // scratch: shaded RGB per point (pad w)

__global__ void __launch_bounds__(256)
shade_kernel(const float* __restrict__ points,
             const float* __restrict__ features,
             const float* __restrict__ normals,
             const float* __restrict__ cam_centers,
             const int*   __restrict__ cloud_idx,
             const float* __restrict__ light_dir,
             int P)
{
    int p = blockIdx.x * blockDim.x + threadIdx.x;
    if (p >= P) return;

    // normalized light direction (uniform; L2/const-cache hit)
    float lx = __ldg(&light_dir[0]);
    float ly = __ldg(&light_dir[1]);
    float lz = __ldg(&light_dir[2]);
    {
        float n  = sqrtf(lx * lx + ly * ly + lz * lz);
        float li = 1.0f / fmaxf(n, 1e-12f);
        lx *= li; ly *= li; lz *= li;
    }

    float nx = normals[3 * p + 0];
    float ny = normals[3 * p + 1];
    float nz = normals[3 * p + 2];

    float ndl     = nx * lx + ny * ly + nz * lz;
    float diffuse = fmaxf(ndl, 0.0f);

    int   c  = cloud_idx[p];
    float vx = cam_centers[3 * c + 0] - points[3 * p + 0];
    float vy = cam_centers[3 * c + 1] - points[3 * p + 1];
    float vz = cam_centers[3 * c + 2] - points[3 * p + 2];
    {
        float n  = sqrtf(vx * vx + vy * vy + vz * vz);
        float vi = 1.0f / fmaxf(n, 1e-12f);
        vx *= vi; vy *= vi; vz *= vi;
    }

    // half vector
    float hx = lx + vx, hy = ly + vy, hz = lz + vz;
    {
        float n  = sqrtf(hx * hx + hy * hy + hz * hz);
        float hi = 1.0f / fmaxf(n, 1e-12f);
        hx *= hi; hy *= hi; hz *= hi;
    }

    float ndh = fmaxf(nx * hx + ny * hy + nz * hz, 0.0f);
    // ndh^32 via exact repeated squaring (no exp/log)
    float x2  = ndh * ndh;
    float x4  = x2 * x2;
    float x8  = x4 * x4;
    float x16 = x8 * x8;
    float spec = x16 * x16;

    float scale = 0.3f + 0.7f * diffuse;   // AMBIENT + DIFFUSE * diffuse
    float sterm = 0.2f * spec;             // SPECULAR * spec

    float r = fminf(fmaxf(features[3 * p + 0] * scale + sterm, 0.0f), 1.0f);
    float g = fminf(fmaxf(features[3 * p + 1] * scale + sterm, 0.0f), 1.0f);
    float b = fminf(fmaxf(features[3 * p + 2] * scale + sterm, 0.0f), 1.0f);

    g_shaded[p] = make_float4(r, g, b, 0.0f);
}

__global__ void __launch_bounds__(256)
composite_kernel(const int* __restrict__ idx,
                 float*     __restrict__ out,
                 int npix, int K)
{
    int i = blockIdx.x * blockDim.x + threadIdx.x;
    if (i >= npix) return;

    int id = __ldg(&idx[(long long)i * K]);   // only fragment 0 matters

    float r, g, b;
    if (id < 0) {
        r = 1.0f; g = 1.0f; b = 1.0f;         // background
    } else {
        float4 s = g_shaded[id];              // L2-resident gather
        r = s.x; g = s.y; b = s.z;
    }
    out[3 * i + 0] = r;
    out[3 * i + 1] = g;
    out[3 * i + 2] = b;
}

extern "C" void kernel_launch(void* const* d_in, const int* in_sizes, int n_in,
                              void* d_out, int out_size)
{
    const int*   idx         = (const int*)  d_in[0];
    const float* points      = (const float*)d_in[1];
    const float* features    = (const float*)d_in[2];
    const float* normals     = (const float*)d_in[3];
    const float* cam_centers = (const float*)d_in[4];
    const int*   cloud_idx   = (const int*)  d_in[5];
    const float* light_dir   = (const float*)d_in[6];
    float*       out         = (float*)d_out;

    int P = in_sizes[5];                 // cloud_idx element count
    if (P > P_MAX) P = P_MAX;            // static scratch bound (shapes fixed)
    int npix = out_size / 3;             // B*H*W
    int K    = in_sizes[0] / npix;       // fragments per pixel

    {
        int threads = 256;
        int blocks  = (P + threads - 1) / threads;
        shade_kernel<<<blocks, threads>>>(points, features, normals,
                                          cam_centers, cloud_idx, light_dir, P);
    }
    {
        int threads = 256;
        int blocks  = (npix + threads - 1) / threads;
        composite_kernel<<<blocks, threads>>>(idx, out, npix, K);
    }
}